// round 5
// baseline (speedup 1.0000x reference)
#include <cuda_runtime.h>
#include <cuda_bf16.h>
#include <cstdint>

#define MDIM 4096
#define NDIM 4096
#define KDIM 2048
#define DEVFN __device__ __forceinline__

// ---------------- device-global scratch (no allocations allowed) ------------
// int8 operands, k-permuted within 64-wide blocks (bits [2:3] <-> [4:5] of k)
static __device__ __align__(256) signed char g_A8[(size_t)MDIM * KDIM];    // qA-128, [M][K] permuted
static __device__ __align__(256) signed char g_B8t[(size_t)NDIM * KDIM];   // (qB-128)^T, [N][K] permuted
static __device__ int g_rowA[MDIM];
static __device__ int g_colB[NDIM];
static __device__ unsigned g_enc[4];  // {Amax, Amin, Bmax, Bmin}, order-encoded
static __device__ float g_rcpA, g_rcpB, g_sAB, g_Kc;
static __device__ int g_zA, g_zB, g_cA, g_cB;

// ---------------- helpers ----------------------------------------------------
DEVFN unsigned encf(float x) {
    unsigned u = __float_as_uint(x);
    return (u & 0x80000000u) ? ~u : (u | 0x80000000u);
}
DEVFN float decf(unsigned e) {
    unsigned u = (e & 0x80000000u) ? (e & 0x7FFFFFFFu) : ~e;
    return __uint_as_float(u);
}
DEVFN int qcenter(float x, float r, int zoff) {
    int i = __float2int_rn(x * r) + zoff;   // round-half-even like jnp.round
    return min(127, max(-128, i));
}
DEVFN int pack4(int a0, int a1, int a2, int a3) {
    return (a0 & 0xFF) | ((a1 & 0xFF) << 8) | ((a2 & 0xFF) << 16) | (a3 << 24);
}
DEVFN uint32_t smem_u32(const void* p) {
    uint32_t a;
    asm("{ .reg .u64 t; cvta.to.shared.u64 t, %1; cvt.u32.u64 %0, t; }" : "=r"(a) : "l"(p));
    return a;
}
DEVFN void cp16(uint32_t dst, const void* src) {
    asm volatile("cp.async.cg.shared.global [%0], [%1], 16;" :: "r"(dst), "l"(src));
}
DEVFN void imma(int& c0, int& c1, int& c2, int& c3,
                int a0, int a1, int a2, int a3, int b0, int b1) {
    asm volatile(
        "mma.sync.aligned.m16n8k32.row.col.s32.s8.s8.s32 "
        "{%0,%1,%2,%3}, {%4,%5,%6,%7}, {%8,%9}, {%0,%1,%2,%3};"
        : "+r"(c0), "+r"(c1), "+r"(c2), "+r"(c3)
        : "r"(a0), "r"(a1), "r"(a2), "r"(a3), "r"(b0), "r"(b1));
}

// ---------------- kernel 0: init ---------------------------------------------
__global__ void init_k() {
    int t = blockIdx.x * blockDim.x + threadIdx.x;
    if (t == 0) {
        g_enc[0] = 0u; g_enc[1] = 0xFFFFFFFFu;
        g_enc[2] = 0u; g_enc[3] = 0xFFFFFFFFu;
    }
    for (int i = t; i < NDIM; i += gridDim.x * blockDim.x) g_colB[i] = 0;
}

// ---------------- kernel 1: min/max ------------------------------------------
__global__ void minmax_k(const float4* __restrict__ x, int n4, int slot) {
    float mx = -3.4e38f, mn = 3.4e38f;
    for (int i = blockIdx.x * blockDim.x + threadIdx.x; i < n4; i += gridDim.x * blockDim.x) {
        float4 v = x[i];
        mx = fmaxf(mx, fmaxf(fmaxf(v.x, v.y), fmaxf(v.z, v.w)));
        mn = fminf(mn, fminf(fminf(v.x, v.y), fminf(v.z, v.w)));
    }
    for (int o = 16; o; o >>= 1) {
        mx = fmaxf(mx, __shfl_xor_sync(0xFFFFFFFFu, mx, o));
        mn = fminf(mn, __shfl_xor_sync(0xFFFFFFFFu, mn, o));
    }
    __shared__ float smx[8], smn[8];
    int wid = threadIdx.x >> 5, lid = threadIdx.x & 31;
    if (lid == 0) { smx[wid] = mx; smn[wid] = mn; }
    __syncthreads();
    if (wid == 0) {
        mx = (lid < 8) ? smx[lid] : -3.4e38f;
        mn = (lid < 8) ? smn[lid] : 3.4e38f;
        for (int o = 4; o; o >>= 1) {
            mx = fmaxf(mx, __shfl_xor_sync(0xFFFFFFFFu, mx, o));
            mn = fminf(mn, __shfl_xor_sync(0xFFFFFFFFu, mn, o));
        }
        if (lid == 0) {
            atomicMax(&g_enc[slot * 2 + 0], encf(mx));
            atomicMin(&g_enc[slot * 2 + 1], encf(mn));
        }
    }
}

// ---------------- kernel 2: quant params --------------------------------------
__global__ void params_k() {
    float Amax = decf(g_enc[0]), Amin = decf(g_enc[1]);
    float Bmax = decf(g_enc[2]), Bmin = decf(g_enc[3]);
    float sA = (Amax - Amin) / 255.0f;
    float sB = (Bmax - Bmin) / 255.0f;
    int zA = (int)rintf(-Amin / sA);
    int zB = (int)rintf(-Bmin / sB);
    g_rcpA = 1.0f / sA;
    g_rcpB = 1.0f / sB;
    g_zA = zA; g_zB = zB;
    int cA = 128 - zA, cB = 128 - zB;
    g_cA = cA; g_cB = cB;
    g_sAB = sA * sB;
    g_Kc = (float)((long long)KDIM * cA * cB);
}

// ---------------- kernel 3: quantize A + rowsum (permuted int8) ---------------
__global__ void quantA_k(const float* __restrict__ A) {
    int row = blockIdx.x;
    int t = threadIdx.x;
    float r = g_rcpA;
    int zoff = g_zA - 128;
    const float4* src = (const float4*)(A + (size_t)row * KDIM);
    int* dst = (int*)(g_A8 + (size_t)row * KDIM);
    int acc = 0;
    #pragma unroll
    for (int it = 0; it < KDIM / 4 / 256; ++it) {
        int i = t + it * 256;           // word index, k0 = 4*i
        float4 v = src[i];
        int a0 = qcenter(v.x, r, zoff), a1 = qcenter(v.y, r, zoff);
        int a2 = qcenter(v.z, r, zoff), a3 = qcenter(v.w, r, zoff);
        acc += a0 + a1 + a2 + a3;
        // permuted word index: swap (i&3) <-> ((i>>2)&3)
        int pw = (i & ~15) | ((i & 3) << 2) | ((i >> 2) & 3);
        dst[pw] = pack4(a0, a1, a2, a3);
    }
    for (int o = 16; o; o >>= 1) acc += __shfl_xor_sync(0xFFFFFFFFu, acc, o);
    __shared__ int sacc[8];
    int wid = t >> 5, lid = t & 31;
    if (lid == 0) sacc[wid] = acc;
    __syncthreads();
    if (t == 0) {
        int s = 0;
        #pragma unroll
        for (int i = 0; i < 8; ++i) s += sacc[i];
        g_rowA[row] = s;
    }
}

// ---------------- kernel 4: quantize + transpose B + colsum (permuted int8) ---
__global__ void quantB_k(const float* __restrict__ B) {
    __shared__ signed char st[64 * 80];   // [n_local][k_local], stride 80
    __shared__ int scs[64];
    int n0 = blockIdx.x * 64, k0 = blockIdx.y * 64;
    int t = threadIdx.x;
    float r = g_rcpB;
    int zoff = g_zB - 128;
    if (t < 64) scs[t] = 0;
    __syncthreads();

    int c = t & 15;    // n-quad within tile
    int kr0 = t >> 4;  // 0..15
    int cs0 = 0, cs1 = 0, cs2 = 0, cs3 = 0;
    #pragma unroll
    for (int it = 0; it < 4; ++it) {
        int kr = kr0 + it * 16;
        float4 v = *(const float4*)(B + (size_t)(k0 + kr) * NDIM + n0 + c * 4);
        int a0 = qcenter(v.x, r, zoff), a1 = qcenter(v.y, r, zoff);
        int a2 = qcenter(v.z, r, zoff), a3 = qcenter(v.w, r, zoff);
        cs0 += a0; cs1 += a1; cs2 += a2; cs3 += a3;
        st[(c * 4 + 0) * 80 + kr] = (signed char)a0;
        st[(c * 4 + 1) * 80 + kr] = (signed char)a1;
        st[(c * 4 + 2) * 80 + kr] = (signed char)a2;
        st[(c * 4 + 3) * 80 + kr] = (signed char)a3;
    }
    cs0 += __shfl_down_sync(0xFFFFFFFFu, cs0, 16);
    cs1 += __shfl_down_sync(0xFFFFFFFFu, cs1, 16);
    cs2 += __shfl_down_sync(0xFFFFFFFFu, cs2, 16);
    cs3 += __shfl_down_sync(0xFFFFFFFFu, cs3, 16);
    if ((t & 31) < 16) {
        atomicAdd(&scs[c * 4 + 0], cs0);
        atomicAdd(&scs[c * 4 + 1], cs1);
        atomicAdd(&scs[c * 4 + 2], cs2);
        atomicAdd(&scs[c * 4 + 3], cs3);
    }
    __syncthreads();
    // write permuted 16B chunks: 64 rows x 4 chunks = 256 threads
    {
        int nl = t >> 2, tt = t & 3;
        uint4 w;
        w.x = *(const unsigned*)&st[nl * 80 + 16 * 0 + 4 * tt];
        w.y = *(const unsigned*)&st[nl * 80 + 16 * 1 + 4 * tt];
        w.z = *(const unsigned*)&st[nl * 80 + 16 * 2 + 4 * tt];
        w.w = *(const unsigned*)&st[nl * 80 + 16 * 3 + 4 * tt];
        *(uint4*)(g_B8t + (size_t)(n0 + nl) * KDIM + k0 + tt * 16) = w;
    }
    if (t < 64) atomicAdd(&g_colB[n0 + t], scs[t]);
}

// ---------------- kernel 5: int8 IMMA GEMM + fused dequant --------------------
// CTA tile 128x128, 8 warps (4x2), warp tile 32x64, BK=64, 4-stage cp.async.
#define STAGE_BYTES 16384           // A 128x64 + B 128x64
#define GEMM_SMEM   65536

__global__ void __launch_bounds__(256, 1)
gemm_k(float* __restrict__ out) {
    extern __shared__ __align__(128) char sm[];
    const int tid = threadIdx.x, lane = tid & 31;
    const int wid = tid >> 5;
    const int g = lane >> 2, t4 = lane & 3;
    const int wm = wid & 3, wn = wid >> 2;

    // block swizzle for L2 reuse: groups of 8 m-tiles x 32 n-tiles
    int gid = blockIdx.x;
    int rem = gid & 255, grp = gid >> 8;
    int m0 = (grp * 8 + (rem & 7)) * 128;
    int n0 = (rem >> 3) * 128;

    const signed char* Ag = g_A8 + (size_t)m0 * KDIM;
    const signed char* Bg = g_B8t + (size_t)n0 * KDIM;

    auto prefetch = [&](int c, int s) {
        char* base = sm + s * STAGE_BYTES;
        int kc = c * 64;
        #pragma unroll
        for (int it = 0; it < 2; ++it) {
            int id = tid + it * 256;
            int row = id >> 2, tt = id & 3;
            cp16(smem_u32(base + row * 64 + tt * 16),
                 Ag + (size_t)row * KDIM + kc + tt * 16);
        }
        #pragma unroll
        for (int it = 0; it < 2; ++it) {
            int id = tid + it * 256;
            int row = id >> 2, tt = id & 3;
            cp16(smem_u32(base + 8192 + row * 64 + tt * 16),
                 Bg + (size_t)row * KDIM + kc + tt * 16);
        }
        asm volatile("cp.async.commit_group;" ::: "memory");
    };

    int acc[2][8][4];
    #pragma unroll
    for (int mt = 0; mt < 2; ++mt)
        #pragma unroll
        for (int nt = 0; nt < 8; ++nt)
            #pragma unroll
            for (int e = 0; e < 4; ++e) acc[mt][nt][e] = 0;

    prefetch(0, 0); prefetch(1, 1); prefetch(2, 2);
    const int NCH = KDIM / 64;  // 32
    for (int c = 0; c < NCH; ++c) {
        asm volatile("cp.async.wait_group 2;" ::: "memory");
        __syncthreads();
        if (c + 3 < NCH) prefetch(c + 3, (c + 3) & 3);
        else asm volatile("cp.async.commit_group;" ::: "memory");

        const char* base = sm + (c & 3) * STAGE_BYTES;
        uint4 Ar[2][2], Br[8];
        #pragma unroll
        for (int mt = 0; mt < 2; ++mt)
            #pragma unroll
            for (int h = 0; h < 2; ++h)
                Ar[mt][h] = *(const uint4*)(base + (wm * 32 + mt * 16 + h * 8 + g) * 64 + t4 * 16);
        #pragma unroll
        for (int nt = 0; nt < 8; ++nt)
            Br[nt] = *(const uint4*)(base + 8192 + (wn * 64 + nt * 8 + g) * 64 + t4 * 16);

        #pragma unroll
        for (int mt = 0; mt < 2; ++mt)
            #pragma unroll
            for (int nt = 0; nt < 8; ++nt) {
                imma(acc[mt][nt][0], acc[mt][nt][1], acc[mt][nt][2], acc[mt][nt][3],
                     (int)Ar[mt][0].x, (int)Ar[mt][1].x, (int)Ar[mt][0].y, (int)Ar[mt][1].y,
                     (int)Br[nt].x, (int)Br[nt].y);
                imma(acc[mt][nt][0], acc[mt][nt][1], acc[mt][nt][2], acc[mt][nt][3],
                     (int)Ar[mt][0].z, (int)Ar[mt][1].z, (int)Ar[mt][0].w, (int)Ar[mt][1].w,
                     (int)Br[nt].z, (int)Br[nt].w);
            }
    }

    // fused dequant epilogue: out = sAB*(acc + cB*rowA[m] + cA*colB[n] + K*cA*cB)
    float sAB = g_sAB, Kc = g_Kc;
    float cAf = (float)g_cA, cBf = (float)g_cB;
    float rc[2][2], cc[8][2];
    #pragma unroll
    for (int mt = 0; mt < 2; ++mt)
        #pragma unroll
        for (int h = 0; h < 2; ++h) {
            int m = m0 + wm * 32 + mt * 16 + h * 8 + g;
            rc[mt][h] = cBf * (float)g_rowA[m] + Kc;
        }
    #pragma unroll
    for (int nt = 0; nt < 8; ++nt)
        #pragma unroll
        for (int e = 0; e < 2; ++e) {
            int n = n0 + wn * 64 + nt * 8 + 2 * t4 + e;
            cc[nt][e] = cAf * (float)g_colB[n];
        }
    #pragma unroll
    for (int mt = 0; mt < 2; ++mt) {
        int mrow0 = m0 + wm * 32 + mt * 16 + g;
        #pragma unroll
        for (int nt = 0; nt < 8; ++nt) {
            int ncol = n0 + wn * 64 + nt * 8 + 2 * t4;
            float2 v0, v1;
            v0.x = sAB * ((float)acc[mt][nt][0] + rc[mt][0] + cc[nt][0]);
            v0.y = sAB * ((float)acc[mt][nt][1] + rc[mt][0] + cc[nt][1]);
            v1.x = sAB * ((float)acc[mt][nt][2] + rc[mt][1] + cc[nt][0]);
            v1.y = sAB * ((float)acc[mt][nt][3] + rc[mt][1] + cc[nt][1]);
            *(float2*)(out + (size_t)mrow0 * NDIM + ncol) = v0;
            *(float2*)(out + (size_t)(mrow0 + 8) * NDIM + ncol) = v1;
        }
    }
}

// ---------------- launcher ----------------------------------------------------
extern "C" void kernel_launch(void* const* d_in, const int* in_sizes, int n_in,
                              void* d_out, int out_size) {
    const float* A = (const float*)d_in[0];
    const float* B = (const float*)d_in[1];
    float* out = (float*)d_out;

    (void)cudaFuncSetAttribute(gemm_k, cudaFuncAttributeMaxDynamicSharedMemorySize, GEMM_SMEM);

    init_k<<<16, 256>>>();
    minmax_k<<<1184, 256>>>((const float4*)A, MDIM * KDIM / 4, 0);
    minmax_k<<<1184, 256>>>((const float4*)B, KDIM * NDIM / 4, 1);
    params_k<<<1, 1>>>();
    quantA_k<<<MDIM, 256>>>(A);
    quantB_k<<<dim3(NDIM / 64, KDIM / 64), 256>>>(B);
    gemm_k<<<(MDIM / 128) * (NDIM / 128), 256, GEMM_SMEM>>>(out);
}

// round 6
// speedup vs baseline: 1.0599x; 1.0599x over previous
#include <cuda_runtime.h>
#include <cuda_bf16.h>
#include <cstdint>

#define MDIM 4096
#define NDIM 4096
#define KDIM 2048
#define DEVFN __device__ __forceinline__

// ---------------- device-global scratch (no allocations allowed) ------------
// int8 operands, k-permuted within 64-wide blocks (bits [2:3] <-> [4:5] of k)
static __device__ __align__(256) signed char g_A8[(size_t)MDIM * KDIM];    // qA-128, [M][K] permuted
static __device__ __align__(256) signed char g_B8t[(size_t)NDIM * KDIM];   // (qB-128)^T, [N][K] permuted
static __device__ int g_rowA[MDIM];
static __device__ int g_colB[NDIM];
static __device__ unsigned g_enc[4];  // {Amax, Amin, Bmax, Bmin}, order-encoded
static __device__ float g_rcpA, g_rcpB, g_sAB, g_Kc;
static __device__ int g_zA, g_zB, g_cA, g_cB;

// ---------------- helpers ----------------------------------------------------
DEVFN unsigned encf(float x) {
    unsigned u = __float_as_uint(x);
    return (u & 0x80000000u) ? ~u : (u | 0x80000000u);
}
DEVFN float decf(unsigned e) {
    unsigned u = (e & 0x80000000u) ? (e & 0x7FFFFFFFu) : ~e;
    return __uint_as_float(u);
}
DEVFN int qcenter(float x, float r, int zoff) {
    int i = __float2int_rn(x * r) + zoff;   // round-half-even like jnp.round
    return min(127, max(-128, i));
}
DEVFN int pack4(int a0, int a1, int a2, int a3) {
    return (a0 & 0xFF) | ((a1 & 0xFF) << 8) | ((a2 & 0xFF) << 16) | (a3 << 24);
}
DEVFN uint32_t smem_u32(const void* p) {
    uint32_t a;
    asm("{ .reg .u64 t; cvta.to.shared.u64 t, %1; cvt.u32.u64 %0, t; }" : "=r"(a) : "l"(p));
    return a;
}
DEVFN void cp16(uint32_t dst, const void* src) {
    asm volatile("cp.async.cg.shared.global [%0], [%1], 16;" :: "r"(dst), "l"(src));
}
DEVFN void imma(int& c0, int& c1, int& c2, int& c3,
                int a0, int a1, int a2, int a3, int b0, int b1) {
    asm volatile(
        "mma.sync.aligned.m16n8k32.row.col.s32.s8.s8.s32 "
        "{%0,%1,%2,%3}, {%4,%5,%6,%7}, {%8,%9}, {%0,%1,%2,%3};"
        : "+r"(c0), "+r"(c1), "+r"(c2), "+r"(c3)
        : "r"(a0), "r"(a1), "r"(a2), "r"(a3), "r"(b0), "r"(b1));
}

// ---------------- kernel 1: min/max ------------------------------------------
// slot 0 initializes the encoded cells for both operands (A is profiled first).
__global__ void minmax_k(const float4* __restrict__ x, int n4, int slot) {
    if (blockIdx.x == 0 && threadIdx.x == 0 && slot == 0) {
        // initialize both slots once (launch order guarantees A pass runs first;
        // atomics from this same kernel race benignly: init values are identities)
    }
    float mx = -3.4e38f, mn = 3.4e38f;
    for (int i = blockIdx.x * blockDim.x + threadIdx.x; i < n4; i += gridDim.x * blockDim.x) {
        float4 v = x[i];
        mx = fmaxf(mx, fmaxf(fmaxf(v.x, v.y), fmaxf(v.z, v.w)));
        mn = fminf(mn, fminf(fminf(v.x, v.y), fminf(v.z, v.w)));
    }
    for (int o = 16; o; o >>= 1) {
        mx = fmaxf(mx, __shfl_xor_sync(0xFFFFFFFFu, mx, o));
        mn = fminf(mn, __shfl_xor_sync(0xFFFFFFFFu, mn, o));
    }
    __shared__ float smx[8], smn[8];
    int wid = threadIdx.x >> 5, lid = threadIdx.x & 31;
    if (lid == 0) { smx[wid] = mx; smn[wid] = mn; }
    __syncthreads();
    if (wid == 0) {
        mx = (lid < 8) ? smx[lid] : -3.4e38f;
        mn = (lid < 8) ? smn[lid] : 3.4e38f;
        for (int o = 4; o; o >>= 1) {
            mx = fmaxf(mx, __shfl_xor_sync(0xFFFFFFFFu, mx, o));
            mn = fminf(mn, __shfl_xor_sync(0xFFFFFFFFu, mn, o));
        }
        if (lid == 0) {
            // encoded max identity is 0, min identity is 0xFFFFFFFF; the harness
            // cannot guarantee scratch init, so use atomicExch-free CAS-less
            // init: g_enc is static zero-initialized at module load; for min we
            // must bias: store encoded-min as ~enc so identity is 0 as well.
            atomicMax(&g_enc[slot * 2 + 0], encf(mx));
            atomicMax(&g_enc[slot * 2 + 1], ~encf(mn));
        }
    }
}

// ---------------- kernel 2: quant params + colB zero --------------------------
__global__ void params_k() {
    int t = blockIdx.x * blockDim.x + threadIdx.x;
    for (int i = t; i < NDIM; i += gridDim.x * blockDim.x) g_colB[i] = 0;
    if (blockIdx.x == 0 && threadIdx.x == 0) {
        float Amax = decf(g_enc[0]), Amin = decf(~g_enc[1]);
        float Bmax = decf(g_enc[2]), Bmin = decf(~g_enc[3]);
        float sA = (Amax - Amin) / 255.0f;
        float sB = (Bmax - Bmin) / 255.0f;
        int zA = (int)rintf(-Amin / sA);
        int zB = (int)rintf(-Bmin / sB);
        g_rcpA = 1.0f / sA;
        g_rcpB = 1.0f / sB;
        g_zA = zA; g_zB = zB;
        int cA = 128 - zA, cB = 128 - zB;
        g_cA = cA; g_cB = cB;
        g_sAB = sA * sB;
        g_Kc = (float)((long long)KDIM * cA * cB);
        // reset encoded cells for the next graph replay (deterministic rerun)
        g_enc[0] = 0u; g_enc[1] = 0u; g_enc[2] = 0u; g_enc[3] = 0u;
    }
}

// ---------------- kernel 3: quantize A + rowsum (permuted int8) ---------------
__global__ void quantA_k(const float* __restrict__ A) {
    int row = blockIdx.x;
    int t = threadIdx.x;
    float r = g_rcpA;
    int zoff = g_zA - 128;
    const float4* src = (const float4*)(A + (size_t)row * KDIM);
    int* dst = (int*)(g_A8 + (size_t)row * KDIM);
    int acc = 0;
    #pragma unroll
    for (int it = 0; it < KDIM / 4 / 256; ++it) {
        int i = t + it * 256;           // word index, k0 = 4*i
        float4 v = src[i];
        int a0 = qcenter(v.x, r, zoff), a1 = qcenter(v.y, r, zoff);
        int a2 = qcenter(v.z, r, zoff), a3 = qcenter(v.w, r, zoff);
        acc += a0 + a1 + a2 + a3;
        // permuted word index: swap (i&3) <-> ((i>>2)&3)
        int pw = (i & ~15) | ((i & 3) << 2) | ((i >> 2) & 3);
        dst[pw] = pack4(a0, a1, a2, a3);
    }
    for (int o = 16; o; o >>= 1) acc += __shfl_xor_sync(0xFFFFFFFFu, acc, o);
    __shared__ int sacc[8];
    int wid = t >> 5, lid = t & 31;
    if (lid == 0) sacc[wid] = acc;
    __syncthreads();
    if (t == 0) {
        int s = 0;
        #pragma unroll
        for (int i = 0; i < 8; ++i) s += sacc[i];
        g_rowA[row] = s;
    }
}

// ---------------- kernel 4: quantize + transpose B + colsum (permuted int8) ---
__global__ void quantB_k(const float* __restrict__ B) {
    __shared__ signed char st[64 * 80];   // [n_local][k_local], stride 80
    __shared__ int scs[64];
    int n0 = blockIdx.x * 64, k0 = blockIdx.y * 64;
    int t = threadIdx.x;
    float r = g_rcpB;
    int zoff = g_zB - 128;
    if (t < 64) scs[t] = 0;
    __syncthreads();

    int c = t & 15;    // n-quad within tile
    int kr0 = t >> 4;  // 0..15
    int cs0 = 0, cs1 = 0, cs2 = 0, cs3 = 0;
    #pragma unroll
    for (int it = 0; it < 4; ++it) {
        int kr = kr0 + it * 16;
        float4 v = *(const float4*)(B + (size_t)(k0 + kr) * NDIM + n0 + c * 4);
        int a0 = qcenter(v.x, r, zoff), a1 = qcenter(v.y, r, zoff);
        int a2 = qcenter(v.z, r, zoff), a3 = qcenter(v.w, r, zoff);
        cs0 += a0; cs1 += a1; cs2 += a2; cs3 += a3;
        st[(c * 4 + 0) * 80 + kr] = (signed char)a0;
        st[(c * 4 + 1) * 80 + kr] = (signed char)a1;
        st[(c * 4 + 2) * 80 + kr] = (signed char)a2;
        st[(c * 4 + 3) * 80 + kr] = (signed char)a3;
    }
    cs0 += __shfl_down_sync(0xFFFFFFFFu, cs0, 16);
    cs1 += __shfl_down_sync(0xFFFFFFFFu, cs1, 16);
    cs2 += __shfl_down_sync(0xFFFFFFFFu, cs2, 16);
    cs3 += __shfl_down_sync(0xFFFFFFFFu, cs3, 16);
    if ((t & 31) < 16) {
        atomicAdd(&scs[c * 4 + 0], cs0);
        atomicAdd(&scs[c * 4 + 1], cs1);
        atomicAdd(&scs[c * 4 + 2], cs2);
        atomicAdd(&scs[c * 4 + 3], cs3);
    }
    __syncthreads();
    // write permuted 16B chunks: 64 rows x 4 chunks = 256 threads
    {
        int nl = t >> 2, tt = t & 3;
        uint4 w;
        w.x = *(const unsigned*)&st[nl * 80 + 16 * 0 + 4 * tt];
        w.y = *(const unsigned*)&st[nl * 80 + 16 * 1 + 4 * tt];
        w.z = *(const unsigned*)&st[nl * 80 + 16 * 2 + 4 * tt];
        w.w = *(const unsigned*)&st[nl * 80 + 16 * 3 + 4 * tt];
        *(uint4*)(g_B8t + (size_t)(n0 + nl) * KDIM + k0 + tt * 16) = w;
    }
    if (t < 64) atomicAdd(&g_colB[n0 + t], scs[t]);
}

// ---------------- kernel 5: int8 IMMA GEMM + fused dequant --------------------
// CTA tile 128x128, 8 warps (4x2), warp tile 32x64, BK=64, 4-stage cp.async.
// Operand loads split by k-half (uint2) to fit 2 CTAs/SM in the register file.
#define STAGE_BYTES 16384           // A 128x64 + B 128x64
#define GEMM_SMEM   65536

__global__ void __launch_bounds__(256, 2)
gemm_k(float* __restrict__ out) {
    extern __shared__ __align__(128) char sm[];
    const int tid = threadIdx.x, lane = tid & 31;
    const int wid = tid >> 5;
    const int g = lane >> 2, t4 = lane & 3;
    const int wm = wid & 3, wn = wid >> 2;

    // block swizzle for L2 reuse: groups of 8 m-tiles x 32 n-tiles
    int gid = blockIdx.x;
    int rem = gid & 255, grp = gid >> 8;
    int m0 = (grp * 8 + (rem & 7)) * 128;
    int n0 = (rem >> 3) * 128;

    const signed char* Ag = g_A8 + (size_t)m0 * KDIM;
    const signed char* Bg = g_B8t + (size_t)n0 * KDIM;

    auto prefetch = [&](int c, int s) {
        char* base = sm + s * STAGE_BYTES;
        int kc = c * 64;
        #pragma unroll
        for (int it = 0; it < 2; ++it) {
            int id = tid + it * 256;
            int row = id >> 2, tt = id & 3;
            cp16(smem_u32(base + row * 64 + tt * 16),
                 Ag + (size_t)row * KDIM + kc + tt * 16);
        }
        #pragma unroll
        for (int it = 0; it < 2; ++it) {
            int id = tid + it * 256;
            int row = id >> 2, tt = id & 3;
            cp16(smem_u32(base + 8192 + row * 64 + tt * 16),
                 Bg + (size_t)row * KDIM + kc + tt * 16);
        }
        asm volatile("cp.async.commit_group;" ::: "memory");
    };

    int acc[2][8][4];
    #pragma unroll
    for (int mt = 0; mt < 2; ++mt)
        #pragma unroll
        for (int nt = 0; nt < 8; ++nt)
            #pragma unroll
            for (int e = 0; e < 4; ++e) acc[mt][nt][e] = 0;

    prefetch(0, 0); prefetch(1, 1); prefetch(2, 2);
    const int NCH = KDIM / 64;  // 32
    for (int c = 0; c < NCH; ++c) {
        asm volatile("cp.async.wait_group 2;" ::: "memory");
        __syncthreads();
        if (c + 3 < NCH) prefetch(c + 3, (c + 3) & 3);
        else asm volatile("cp.async.commit_group;" ::: "memory");

        const char* base = sm + (c & 3) * STAGE_BYTES;
        // two k32 halves; uint2 fragments keep live operand regs at 24 words
        #pragma unroll
        for (int half = 0; half < 2; ++half) {
            uint2 Ar[2][2], Br[8];
            #pragma unroll
            for (int mt = 0; mt < 2; ++mt)
                #pragma unroll
                for (int h = 0; h < 2; ++h)
                    Ar[mt][h] = *(const uint2*)(base +
                        (wm * 32 + mt * 16 + h * 8 + g) * 64 + t4 * 16 + half * 8);
            #pragma unroll
            for (int nt = 0; nt < 8; ++nt)
                Br[nt] = *(const uint2*)(base + 8192 +
                    (wn * 64 + nt * 8 + g) * 64 + t4 * 16 + half * 8);
            #pragma unroll
            for (int mt = 0; mt < 2; ++mt)
                #pragma unroll
                for (int nt = 0; nt < 8; ++nt)
                    imma(acc[mt][nt][0], acc[mt][nt][1], acc[mt][nt][2], acc[mt][nt][3],
                         (int)Ar[mt][0].x, (int)Ar[mt][1].x, (int)Ar[mt][0].y, (int)Ar[mt][1].y,
                         (int)Br[nt].x, (int)Br[nt].y);
        }
    }

    // fused dequant epilogue: out = sAB*(acc + cB*rowA[m] + cA*colB[n] + K*cA*cB)
    float sAB = g_sAB, Kc = g_Kc;
    float cAf = (float)g_cA, cBf = (float)g_cB;
    float rc[2][2], cc[8][2];
    #pragma unroll
    for (int mt = 0; mt < 2; ++mt)
        #pragma unroll
        for (int h = 0; h < 2; ++h) {
            int m = m0 + wm * 32 + mt * 16 + h * 8 + g;
            rc[mt][h] = cBf * (float)g_rowA[m] + Kc;
        }
    #pragma unroll
    for (int nt = 0; nt < 8; ++nt)
        #pragma unroll
        for (int e = 0; e < 2; ++e) {
            int n = n0 + wn * 64 + nt * 8 + 2 * t4 + e;
            cc[nt][e] = cAf * (float)g_colB[n];
        }
    #pragma unroll
    for (int mt = 0; mt < 2; ++mt) {
        int mrow0 = m0 + wm * 32 + mt * 16 + g;
        #pragma unroll
        for (int nt = 0; nt < 8; ++nt) {
            int ncol = n0 + wn * 64 + nt * 8 + 2 * t4;
            float2 v0, v1;
            v0.x = sAB * ((float)acc[mt][nt][0] + rc[mt][0] + cc[nt][0]);
            v0.y = sAB * ((float)acc[mt][nt][1] + rc[mt][0] + cc[nt][1]);
            v1.x = sAB * ((float)acc[mt][nt][2] + rc[mt][1] + cc[nt][0]);
            v1.y = sAB * ((float)acc[mt][nt][3] + rc[mt][1] + cc[nt][1]);
            *(float2*)(out + (size_t)mrow0 * NDIM + ncol) = v0;
            *(float2*)(out + (size_t)(mrow0 + 8) * NDIM + ncol) = v1;
        }
    }
}

// ---------------- launcher ----------------------------------------------------
// 6 launches; gemm_k is launch index 5 so the profiler's "-s 5 -c 1" window
// captures the GEMM.
extern "C" void kernel_launch(void* const* d_in, const int* in_sizes, int n_in,
                              void* d_out, int out_size) {
    const float* A = (const float*)d_in[0];
    const float* B = (const float*)d_in[1];
    float* out = (float*)d_out;

    (void)cudaFuncSetAttribute(gemm_k, cudaFuncAttributeMaxDynamicSharedMemorySize, GEMM_SMEM);

    minmax_k<<<1184, 256>>>((const float4*)A, MDIM * KDIM / 4, 0);
    minmax_k<<<1184, 256>>>((const float4*)B, KDIM * NDIM / 4, 1);
    params_k<<<16, 256>>>();
    quantA_k<<<MDIM, 256>>>(A);
    quantB_k<<<dim3(NDIM / 64, KDIM / 64), 256>>>(B);
    gemm_k<<<(MDIM / 128) * (NDIM / 128), 256, GEMM_SMEM>>>(out);
}